// round 8
// baseline (speedup 1.0000x reference)
#include <cuda_runtime.h>
#include <cstdint>

#define BATCH 128
#define ITEMS 8000
#define CONC  128
#define EMB   32
#define TI    64
#define NBLK  (ITEMS / TI)    // 125

#define W1S 36      // w1 row stride
#define IES 36      // item_emb row stride
#define QS  136     // Q tile row stride
#define QWS 136     // qw' (permuted) row stride
#define AJ  272     // A' row-pair stride (16 mod 32 -> conflict-free frags)
#define AQ  2176    // A' 16-row-block stride

// float-offset smem map
#define OFF_A    0        // 8*2176 = 17408 (stuC in fragment order)
#define OFF_QW   17408    // 64*136 = 8704  (qw, column-pair permuted)
#define OFF_W1   26112    // 128*36 = 4608
#define OFF_IE   30720    // 64*36  = 2304
#define OFF_Q    33024    // 64*136 = 8704
#define OFF_EMB2 41728    // 128*32 = 4096 (gathered student embeddings)
#define OFF_B1   45824    // 128
#define OFF_WP   45952    // 128
#define OFF_GQ   46080    // 128
#define OFF_ZC   46208    // 64
#define OFF_QA   46272    // 64
#define OFF_DISC 46336    // 64
#define OFF_GSU  46400    // 128
#define OFF_IDX  46528    // 128 (int)
#define SMEM_FLOATS 46656
#define SMEM_BYTES  (SMEM_FLOATS * 4)   // 186624 B, 1 CTA/SM

__device__ __forceinline__ float sigt(float x) {          // 1 MUFU sigmoid
    float t;
    asm("tanh.approx.f32 %0, %1;" : "=f"(t) : "f"(x * 0.5f));
    return fmaf(0.5f, t, 0.5f);
}
__device__ __forceinline__ void fma2(unsigned long long& acc,
                                     unsigned long long a, unsigned long long b) {
    asm("fma.rn.f32x2 %0, %1, %2, %0;" : "+l"(acc) : "l"(a), "l"(b));
}
__device__ __forceinline__ float tf32_rna(float x) {
    uint32_t t;
    asm("cvt.rna.tf32.f32 %0, %1;" : "=r"(t) : "f"(x));
    return __uint_as_float(t);
}
__device__ __forceinline__ void mma_tf32(float* d, const float4 a, const float2 b) {
    asm("mma.sync.aligned.m16n8k8.row.col.f32.tf32.tf32.f32 "
        "{%0,%1,%2,%3}, {%4,%5,%6,%7}, {%8,%9}, {%0,%1,%2,%3};"
        : "+f"(d[0]), "+f"(d[1]), "+f"(d[2]), "+f"(d[3])
        : "r"(__float_as_uint(a.x)), "r"(__float_as_uint(a.y)),
          "r"(__float_as_uint(a.z)), "r"(__float_as_uint(a.w)),
          "r"(__float_as_uint(b.x)), "r"(__float_as_uint(b.y)));
}
__device__ __forceinline__ void cp16(float* dst_smem, const float* src) {
    unsigned d = (unsigned)__cvta_generic_to_shared(dst_smem);
    asm volatile("cp.async.ca.shared.global [%0], [%1], 16;\n" :: "r"(d), "l"(src));
}

// ---------------------------------------------------------------------------
// ONE fused kernel, 512 threads per 64-item tile.
//   prefetch g0: w1/ie/Q/params; g1: gathered stu_emb (after idx lands)
//   phase B: itemC + qw' (permuted) + per-item scalars
//   phase A: stuC -> fragment-order smem (recomputed per CTA, tanh sigmoid)
//   phase C: stuC @ qw'^T via mma.sync tf32 (1 LDS.128 + 1 LDS.64 per 2 frags)
//   epilogue fused (tanh sigmoids)
// ---------------------------------------------------------------------------
__global__ void __launch_bounds__(512, 1) main_kernel(
    const int*   __restrict__ stu_list,
    const float* __restrict__ stu_emb,
    const float* __restrict__ item_emb,
    const float* __restrict__ disc,
    const float* __restrict__ Q,
    const float* __restrict__ w1,
    const float* __restrict__ b1,
    const float* __restrict__ wp,
    const float* __restrict__ bp,
    const float* __restrict__ gw_stu,
    const float* __restrict__ gw_Q,
    const float* __restrict__ w2,
    const float* __restrict__ b2,
    float* __restrict__ out)
{
    extern __shared__ float sm[];
    float* s_A    = sm + OFF_A;
    float* s_qw   = sm + OFF_QW;
    float* s_w1   = sm + OFF_W1;
    float* s_ie   = sm + OFF_IE;
    float* s_Q    = sm + OFF_Q;
    float* s_emb2 = sm + OFF_EMB2;
    float* s_b1   = sm + OFF_B1;
    float* s_wp   = sm + OFF_WP;
    float* s_gq   = sm + OFF_GQ;
    float* s_zc   = sm + OFF_ZC;
    float* s_qa   = sm + OFF_QA;
    float* s_disc = sm + OFF_DISC;
    float* s_gsu  = sm + OFF_GSU;
    int*   s_idx  = (int*)(sm + OFF_IDX);

    const int tid  = threadIdx.x;
    const int wid  = tid >> 5;
    const int lane = tid & 31;
    const int i0   = blockIdx.x * TI;

    // ---- early index load (LDG, hidden behind prefetch issue) ----
    int myidx = 0;
    if (tid < BATCH) { myidx = stu_list[tid] - 1; s_idx[tid] = myidx; }

    // ---- group 0: everything phase B needs ----
    for (int j = tid; j < CONC * 8; j += 512)
        cp16(s_w1 + (j >> 3) * W1S + (j & 7) * 4, w1 + j * 4);
    for (int j = tid; j < TI * 8; j += 512)
        cp16(s_ie + (j >> 3) * IES + (j & 7) * 4,
             item_emb + (size_t)i0 * EMB + j * 4);
    for (int j = tid; j < TI * 32; j += 512)
        cp16(s_Q + (j >> 5) * QS + (j & 31) * 4,
             Q + (size_t)(i0 + (j >> 5)) * CONC + (j & 31) * 4);
    if (tid < 32)       cp16(s_b1 + tid * 4, b1 + tid * 4);
    else if (tid < 64)  cp16(s_wp + (tid - 32) * 4, wp + (tid - 32) * 4);
    else if (tid < 96)  cp16(s_gq + (tid - 64) * 4, gw_Q + (tid - 64) * 4);
    else if (tid < 112) cp16(s_disc + (tid - 96) * 4, disc + i0 + (tid - 96) * 4);
    asm volatile("cp.async.commit_group;\n" ::: "memory");

    // gw_stu gather (plain LDG chain, consumed only in epilogue)
    if (tid < BATCH) s_gsu[tid] = gw_stu[myidx];

    __syncthreads();   // s_idx visible to all

    // ---- group 1: gathered student embeddings ----
    for (int j = tid; j < BATCH * 8; j += 512) {
        const int r = j >> 3, q = j & 7;
        cp16(s_emb2 + r * EMB + q * 4, stu_emb + (size_t)s_idx[r] * EMB + q * 4);
    }
    asm volatile("cp.async.commit_group;\n" ::: "memory");

    const float bpv = bp[0];
    asm volatile("cp.async.wait_group 1;\n" ::: "memory");
    __syncthreads();

    // ---- phase B: item ii = tid>>3, concepts c = (tid&7) + 8s ----
    {
        const int ii   = tid >> 3;
        const int cr   = tid & 7;
        const int posr = 2 * (cr & 3) + ((cr >> 2) & 1);

        ulonglong2 ier[8];
        const ulonglong2* iep = (const ulonglong2*)(s_ie + ii * IES);
#pragma unroll
        for (int k = 0; k < 8; k++) ier[k] = iep[k];

        float prod = 0.0f, qa = 0.0f;
#pragma unroll 4
        for (int s = 0; s < 16; s++) {
            const int c = cr + 8 * s;
            const ulonglong2* wr = (const ulonglong2*)(s_w1 + c * W1S);
            unsigned long long za = 0ull, zb = 0ull;
#pragma unroll
            for (int k = 0; k < 8; k++) {
                ulonglong2 w = wr[k];
                fma2(za, ier[k].x, w.x);
                fma2(zb, ier[k].y, w.y);
            }
            float la, ha, lb, hb;
            asm("mov.b64 {%0, %1}, %2;" : "=f"(la), "=f"(ha) : "l"(za));
            asm("mov.b64 {%0, %1}, %2;" : "=f"(lb), "=f"(hb) : "l"(zb));
            const float z  = (la + ha) + (lb + hb) + s_b1[c];
            const float ic = sigt(z);
            const float qv = s_Q[ii * QS + c];
            const float qwv = qv * s_wp[c];
            s_qw[ii * QWS + 8 * s + posr] = tf32_rna(qwv);
            prod = fmaf(qwv, ic, prod);
            qa   = fmaf(qv, s_gq[c], qa);
        }
#pragma unroll
        for (int off = 4; off > 0; off >>= 1) {
            prod += __shfl_down_sync(0xffffffffu, prod, off, 8);
            qa   += __shfl_down_sync(0xffffffffu, qa,   off, 8);
        }
        if (cr == 0) {
            s_zc[ii] = fmaf(-s_disc[ii], prod, bpv);
            s_qa[ii] = qa;
        }
    }
    asm volatile("cp.async.wait_group 0;\n" ::: "memory");
    __syncthreads();

    // ---- phase A: stuC -> fragment-order A' ----
    {
        const int c = tid & 127;
        const int p = tid >> 7;
        const int colbase = (c >> 3) * 16 + (c & 3) * 4 + ((c >> 2) & 1) * 2;
        const float b1c = s_b1[c];

        unsigned long long w1r[16];
        const ulonglong2* wr = (const ulonglong2*)(s_w1 + c * W1S);
#pragma unroll
        for (int k = 0; k < 8; k++) {
            ulonglong2 w = wr[k];
            w1r[2 * k]     = w.x;
            w1r[2 * k + 1] = w.y;
        }
#pragma unroll 2
        for (int n = 0; n < 32; n++) {
            const int b = p + 4 * n;
            const ulonglong2* eb = (const ulonglong2*)(s_emb2 + b * EMB);
            unsigned long long za = 0ull, zb = 0ull;
#pragma unroll
            for (int k = 0; k < 8; k++) {
                ulonglong2 e = eb[k];
                fma2(za, e.x, w1r[2 * k]);
                fma2(zb, e.y, w1r[2 * k + 1]);
            }
            float la, ha, lb, hb;
            asm("mov.b64 {%0, %1}, %2;" : "=f"(la), "=f"(ha) : "l"(za));
            asm("mov.b64 {%0, %1}, %2;" : "=f"(lb), "=f"(hb) : "l"(zb));
            const float z = (la + ha) + (lb + hb) + b1c;
            const int rb = b & 15;
            s_A[(b >> 4) * AQ + (rb & 7) * AJ + colbase + (rb >> 3)] =
                tf32_rna(sigt(z));
        }
    }
    __syncthreads();

    // ---- phase C: mma.sync tf32, warp tile 32(b) x 16(i) ----
    const int wm  = wid & 3;
    const int wn  = wid >> 2;
    const int gid = lane >> 2;
    const int tig = lane & 3;

    float acc[2][2][4];
#pragma unroll
    for (int mi = 0; mi < 2; mi++)
#pragma unroll
        for (int ni = 0; ni < 2; ni++)
#pragma unroll
            for (int r = 0; r < 4; r++) acc[mi][ni][r] = 0.0f;

    const float* pa = s_A  + (2 * wm) * AQ + gid * AJ + tig * 4;
    const float* pb = s_qw + (16 * wn + gid) * QWS + tig * 2;
#pragma unroll
    for (int k = 0; k < 16; k++) {
        const float4 a0 = *(const float4*)(pa + k * 16);
        const float4 a1 = *(const float4*)(pa + AQ + k * 16);
        const float2 b0 = *(const float2*)(pb + k * 8);
        const float2 b1v = *(const float2*)(pb + 8 * QWS + k * 8);
        mma_tf32(acc[0][0], a0, b0);
        mma_tf32(acc[0][1], a0, b1v);
        mma_tf32(acc[1][0], a1, b0);
        mma_tf32(acc[1][1], a1, b1v);
    }

    // ---- fused epilogue ----
    const float w2v = w2[0];
    const float b2v = b2[0];
#pragma unroll
    for (int mi = 0; mi < 2; mi++)
#pragma unroll
        for (int h = 0; h < 2; h++) {
            const int row = 32 * wm + 16 * mi + 8 * h + gid;
            const float gs = s_gsu[row];
            float* orow = out + (size_t)row * ITEMS + i0;
#pragma unroll
            for (int ni = 0; ni < 2; ni++) {
                const int col = 16 * wn + 8 * ni + 2 * tig;
                float res[2];
#pragma unroll
                for (int e = 0; e < 2; e++) {
                    const int il = col + e;
                    const float t1 = acc[mi][ni][2 * h + e];
                    const float z  = fmaf(s_disc[il], t1, s_zc[il]);
                    const float P  = sigt(z);
                    const float g1 = sigt(gs + s_qa[il]);
                    const float g2 = sigt(fmaf(g1, w2v, b2v));
                    res[e] = g2 + (1.0f - g2) * P;
                }
                *(float2*)(orow + col) = make_float2(res[0], res[1]);
            }
        }
}

// ---------------------------------------------------------------------------
extern "C" void kernel_launch(void* const* d_in, const int* in_sizes, int n_in,
                              void* d_out, int out_size) {
    const int*   stu_list = (const int*)  d_in[0];
    const float* stu_emb  = (const float*)d_in[1];
    const float* item_emb = (const float*)d_in[2];
    const float* disc     = (const float*)d_in[3];
    const float* Q        = (const float*)d_in[4];
    const float* w1       = (const float*)d_in[5];
    const float* b1       = (const float*)d_in[6];
    const float* wp       = (const float*)d_in[7];
    const float* bp       = (const float*)d_in[8];
    const float* gw_stu   = (const float*)d_in[9];
    const float* gw_Q     = (const float*)d_in[10];
    const float* w2       = (const float*)d_in[11];
    const float* b2       = (const float*)d_in[12];
    float* out = (float*)d_out;

    cudaFuncSetAttribute(main_kernel, cudaFuncAttributeMaxDynamicSharedMemorySize,
                         SMEM_BYTES);
    main_kernel<<<NBLK, 512, SMEM_BYTES>>>(stu_list, stu_emb, item_emb, disc, Q,
                                           w1, b1, wp, bp, gw_stu, gw_Q, w2, b2,
                                           out);
}

// round 10
// speedup vs baseline: 1.3702x; 1.3702x over previous
#include <cuda_runtime.h>
#include <cstdint>

#define BATCH 128
#define ITEMS 8000
#define CONC  128
#define EMB   32
#define TI    64
#define NBLK  (ITEMS / TI)    // 125

#define W1S 36      // w1 row stride
#define IES 36      // item_emb row stride
#define QS  136     // Q tile row stride
#define QWS 136     // qw' (permuted) row stride
#define AJ  272     // A' smem row-pair stride (conflict-free fragments)
#define AQ  2176    // A' smem 16-row-block stride
#define AJG 256     // A' gmem row-pair stride
#define AQG 2048    // A' gmem 16-row-block stride

// float-offset smem map (main kernel)
#define OFF_A    0        // 8*2176 = 17408 (stuC, fragment order)
#define OFF_QW   17408    // 64*136 = 8704  (qw, column-pair permuted)
#define OFF_W1   26112    // 128*36 = 4608
#define OFF_IE   30720    // 64*36  = 2304
#define OFF_Q    33024    // 64*136 = 8704
#define OFF_B1   41728    // 128
#define OFF_WP   41856    // 128
#define OFF_GQ   41984    // 128
#define OFF_ZC   42112    // 64
#define OFF_QA   42176    // 64
#define OFF_DISC 42240    // 64
#define OFF_GSU  42304    // 128
#define OFF_POLY 42432    // 8 (F0, D1..D6)
#define SMEM_FLOATS 42440
#define SMEM_BYTES  (SMEM_FLOATS * 4)   // 169760 B

__device__ float g_stuC[BATCH * CONC];   // tf32-rounded, FRAGMENT order
__device__ float g_gsu[BATCH];

__device__ __forceinline__ float sigmoidf(float x) {      // accurate
    return __fdividef(1.0f, 1.0f + __expf(-x));
}
__device__ __forceinline__ float sigt(float x) {          // 1 MUFU
    float t;
    asm("tanh.approx.f32 %0, %1;" : "=f"(t) : "f"(x * 0.5f));
    return fmaf(0.5f, t, 0.5f);
}
__device__ __forceinline__ void fma2(unsigned long long& acc,
                                     unsigned long long a, unsigned long long b) {
    asm("fma.rn.f32x2 %0, %1, %2, %0;" : "+l"(acc) : "l"(a), "l"(b));
}
__device__ __forceinline__ float tf32_rna(float x) {
    uint32_t t;
    asm("cvt.rna.tf32.f32 %0, %1;" : "=r"(t) : "f"(x));
    return __uint_as_float(t);
}
__device__ __forceinline__ void mma_tf32(float* d, const float4 a, const float2 b) {
    asm("mma.sync.aligned.m16n8k8.row.col.f32.tf32.tf32.f32 "
        "{%0,%1,%2,%3}, {%4,%5,%6,%7}, {%8,%9}, {%0,%1,%2,%3};"
        : "+f"(d[0]), "+f"(d[1]), "+f"(d[2]), "+f"(d[3])
        : "r"(__float_as_uint(a.x)), "r"(__float_as_uint(a.y)),
          "r"(__float_as_uint(a.z)), "r"(__float_as_uint(a.w)),
          "r"(__float_as_uint(b.x)), "r"(__float_as_uint(b.y)));
}
__device__ __forceinline__ void cp16(float* dst_smem, const float* src) {
    unsigned d = (unsigned)__cvta_generic_to_shared(dst_smem);
    asm volatile("cp.async.ca.shared.global [%0], [%1], 16;\n" :: "r"(d), "l"(src));
}
// fragment-order index for stuC[b][c]
__device__ __forceinline__ int fragIdxG(int b, int c) {
    const int rb = b & 15;
    const int col = (c >> 3) * 16 + (c & 3) * 4 + ((c >> 2) & 1) * 2 + (rb >> 3);
    return (b >> 4) * AQG + (rb & 7) * AJG + col;
}

// ---------------------------------------------------------------------------
// Kernel 1: 16 CTAs x 512 thr; 8 students per CTA.
// Writes g_stuC in fragment order; triggers dependent launch at entry.
// ---------------------------------------------------------------------------
__global__ void __launch_bounds__(512) stu_kernel(
    const int*   __restrict__ stu_list,
    const float* __restrict__ stu_emb,
    const float* __restrict__ w1,
    const float* __restrict__ b1,
    const float* __restrict__ gw_stu)
{
    __shared__ float s_w1[CONC * 33];
    __shared__ float s_emb[8 * EMB];
    __shared__ int   s_sidx[8];

    asm volatile("griddepcontrol.launch_dependents;");

    const int t  = threadIdx.x;
    const int b0 = blockIdx.x * 8;

    if (t < 8) {
        const int idx = stu_list[b0 + t] - 1;
        s_sidx[t] = idx;
        g_gsu[b0 + t] = gw_stu[idx];
    }
    for (int j = t; j < CONC * EMB; j += 512)
        s_w1[(j >> 5) * 33 + (j & 31)] = w1[j];
    __syncthreads();
    if (t < 8 * EMB)
        s_emb[t] = stu_emb[(size_t)s_sidx[t >> 5] * EMB + (t & 31)];
    __syncthreads();

    const int c  = t & 127;
    const int sl = t >> 7;                // 0..3
    const float b1c = b1[c];
#pragma unroll
    for (int r = 0; r < 2; r++) {
        const int s = sl + 4 * r;
        float z = b1c;
#pragma unroll
        for (int k = 0; k < EMB; k++)
            z = fmaf(s_emb[s * EMB + k], s_w1[c * 33 + k], z);
        g_stuC[fragIdxG(b0 + s, c)] = tf32_rna(sigmoidf(z));
    }
}

// ---------------------------------------------------------------------------
// Kernel 2 (PDL dependent), 512 threads per 64-item tile.
// ---------------------------------------------------------------------------
__global__ void __launch_bounds__(512, 1) main_kernel(
    const float* __restrict__ item_emb,
    const float* __restrict__ disc,
    const float* __restrict__ Q,
    const float* __restrict__ w1,
    const float* __restrict__ b1,
    const float* __restrict__ wp,
    const float* __restrict__ bp,
    const float* __restrict__ gw_Q,
    const float* __restrict__ w2,
    const float* __restrict__ b2,
    float* __restrict__ out)
{
    extern __shared__ float sm[];
    float* s_A    = sm + OFF_A;
    float* s_qw   = sm + OFF_QW;
    float* s_w1   = sm + OFF_W1;
    float* s_ie   = sm + OFF_IE;
    float* s_Q    = sm + OFF_Q;
    float* s_b1   = sm + OFF_B1;
    float* s_wp   = sm + OFF_WP;
    float* s_gq   = sm + OFF_GQ;
    float* s_zc   = sm + OFF_ZC;
    float* s_qa   = sm + OFF_QA;
    float* s_disc = sm + OFF_DISC;
    float* s_gsu  = sm + OFF_GSU;
    float* s_poly = sm + OFF_POLY;

    const int tid  = threadIdx.x;
    const int wid  = tid >> 5;
    const int lane = tid & 31;
    const int i0   = blockIdx.x * TI;

    // ---- group 0: everything phase B needs (independent of stu_kernel) ----
    for (int j = tid; j < CONC * 8; j += 512)
        cp16(s_w1 + (j >> 3) * W1S + (j & 7) * 4, w1 + j * 4);
    for (int j = tid; j < TI * 8; j += 512)
        cp16(s_ie + (j >> 3) * IES + (j & 7) * 4,
             item_emb + (size_t)i0 * EMB + j * 4);
    for (int j = tid; j < TI * 32; j += 512)
        cp16(s_Q + (j >> 5) * QS + (j & 31) * 4,
             Q + (size_t)(i0 + (j >> 5)) * CONC + (j & 31) * 4);
    if (tid < 32)       cp16(s_b1 + tid * 4, b1 + tid * 4);
    else if (tid < 64)  cp16(s_wp + (tid - 32) * 4, wp + (tid - 32) * 4);
    else if (tid < 96)  cp16(s_gq + (tid - 64) * 4, gw_Q + (tid - 64) * 4);
    else if (tid < 112) cp16(s_disc + (tid - 96) * 4, disc + i0 + (tid - 96) * 4);
    asm volatile("cp.async.commit_group;\n" ::: "memory");

    const float bpv = bp[0];

    // ---- g2 degree-6 Newton interpolation setup (warp 0) ----
    if (wid == 0) {
        const float w2v = w2[0];
        const float b2v = b2[0];
        const float h = 1.0f / 6.0f;
        float fk = sigmoidf(fmaf(w2v, h * (float)(lane < 7 ? lane : 0), b2v));
        const float f0 = __shfl_sync(0xffffffffu, fk, 0);
        const float f1 = __shfl_sync(0xffffffffu, fk, 1);
        const float f2 = __shfl_sync(0xffffffffu, fk, 2);
        const float f3 = __shfl_sync(0xffffffffu, fk, 3);
        const float f4 = __shfl_sync(0xffffffffu, fk, 4);
        const float f5 = __shfl_sync(0xffffffffu, fk, 5);
        const float f6 = __shfl_sync(0xffffffffu, fk, 6);
        if (lane == 0) {
            const float d1 = f1 - f0;
            const float d2 = f2 - 2.0f * f1 + f0;
            const float d3 = f3 - 3.0f * f2 + 3.0f * f1 - f0;
            const float d4 = f4 - 4.0f * f3 + 6.0f * f2 - 4.0f * f1 + f0;
            const float d5 = f5 - 5.0f * f4 + 10.0f * f3 - 10.0f * f2
                             + 5.0f * f1 - f0;
            const float d6 = f6 - 6.0f * f5 + 15.0f * f4 - 20.0f * f3
                             + 15.0f * f2 - 6.0f * f1 + f0;
            s_poly[0] = f0;
            s_poly[1] = d1;
            s_poly[2] = d2 * 0.5f;
            s_poly[3] = d3 * (1.0f / 6.0f);
            s_poly[4] = d4 * (1.0f / 24.0f);
            s_poly[5] = d5 * (1.0f / 120.0f);
            s_poly[6] = d6 * (1.0f / 720.0f);
        }
    }

    asm volatile("cp.async.wait_group 0;\n" ::: "memory");
    __syncthreads();

    // ---- phase B: item ii = tid>>3, concepts c = (tid&7) + 8s ----
    {
        const int ii   = tid >> 3;
        const int cr   = tid & 7;
        const int posr = 2 * (cr & 3) + ((cr >> 2) & 1);

        ulonglong2 ier[8];
        const ulonglong2* iep = (const ulonglong2*)(s_ie + ii * IES);
#pragma unroll
        for (int k = 0; k < 8; k++) ier[k] = iep[k];

        float prod = 0.0f, qa = 0.0f;
#pragma unroll 4
        for (int s = 0; s < 16; s++) {
            const int c = cr + 8 * s;
            const ulonglong2* wr = (const ulonglong2*)(s_w1 + c * W1S);
            unsigned long long za = 0ull, zb = 0ull;
#pragma unroll
            for (int k = 0; k < 8; k++) {
                ulonglong2 w = wr[k];
                fma2(za, ier[k].x, w.x);
                fma2(zb, ier[k].y, w.y);
            }
            float la, ha, lb, hb;
            asm("mov.b64 {%0, %1}, %2;" : "=f"(la), "=f"(ha) : "l"(za));
            asm("mov.b64 {%0, %1}, %2;" : "=f"(lb), "=f"(hb) : "l"(zb));
            const float z  = (la + ha) + (lb + hb) + s_b1[c];
            const float ic = sigt(z);
            const float qv = s_Q[ii * QS + c];
            const float qwv = qv * s_wp[c];
            s_qw[ii * QWS + 8 * s + posr] = tf32_rna(qwv);
            prod = fmaf(qwv, ic, prod);
            qa   = fmaf(qv, s_gq[c], qa);
        }
#pragma unroll
        for (int off = 4; off > 0; off >>= 1) {
            prod += __shfl_down_sync(0xffffffffu, prod, off, 8);
            qa   += __shfl_down_sync(0xffffffffu, qa,   off, 8);
        }
        if (cr == 0) {
            s_zc[ii] = fmaf(-s_disc[ii], prod, bpv);
            s_qa[ii] = qa;
        }
    }

    // ---- wait for stu_kernel results, then pull them in ----
    asm volatile("griddepcontrol.wait;" ::: "memory");
    for (int j = tid; j < 4096; j += 512)      // 16384 floats = 4096 x 16B
        cp16(s_A + (j >> 9) * AQ + ((j >> 6) & 7) * AJ + (j & 63) * 4,
             g_stuC + j * 4);
    if (tid < 32) cp16(s_gsu + tid * 4, g_gsu + tid * 4);
    asm volatile("cp.async.commit_group;\n" ::: "memory");
    asm volatile("cp.async.wait_group 0;\n" ::: "memory");
    __syncthreads();

    // ---- phase C: mma.sync tf32, warp tile 32(b) x 16(i) ----
    const int wm  = wid & 3;
    const int wn  = wid >> 2;
    const int gid = lane >> 2;
    const int tig = lane & 3;

    float acc[2][2][4];
#pragma unroll
    for (int mi = 0; mi < 2; mi++)
#pragma unroll
        for (int ni = 0; ni < 2; ni++)
#pragma unroll
            for (int r = 0; r < 4; r++) acc[mi][ni][r] = 0.0f;

    const float* pa = s_A  + (2 * wm) * AQ + gid * AJ + tig * 4;
    const float* pb = s_qw + (16 * wn + gid) * QWS + tig * 2;
#pragma unroll
    for (int k = 0; k < 16; k++) {
        const float4 a0 = *(const float4*)(pa + k * 16);
        const float4 a1 = *(const float4*)(pa + AQ + k * 16);
        const float2 b0 = *(const float2*)(pb + k * 8);
        const float2 b1v = *(const float2*)(pb + 8 * QWS + k * 8);
        mma_tf32(acc[0][0], a0, b0);
        mma_tf32(acc[0][1], a0, b1v);
        mma_tf32(acc[1][0], a1, b0);
        mma_tf32(acc[1][1], a1, b1v);
    }

    // ---- fused epilogue: 2 MUFU + degree-6 poly g2 per output ----
    const float F0 = s_poly[0], D1 = s_poly[1], D2 = s_poly[2],
                D3 = s_poly[3], D4 = s_poly[4], D5 = s_poly[5],
                D6 = s_poly[6];
#pragma unroll
    for (int mi = 0; mi < 2; mi++)
#pragma unroll
        for (int h = 0; h < 2; h++) {
            const int row = 32 * wm + 16 * mi + 8 * h + gid;
            const float gs = s_gsu[row];
            float* orow = out + (size_t)row * ITEMS + i0;
#pragma unroll
            for (int ni = 0; ni < 2; ni++) {
                const int col = 16 * wn + 8 * ni + 2 * tig;
                float res[2];
#pragma unroll
                for (int e = 0; e < 2; e++) {
                    const int il = col + e;
                    const float t1 = acc[mi][ni][2 * h + e];
                    const float z  = fmaf(s_disc[il], t1, s_zc[il]);
                    const float P  = sigt(z);
                    const float g1 = sigt(gs + s_qa[il]);
                    // g2 via degree-6 Newton interp of sigmoid(w2*u+b2), v=6*g1
                    const float v = 6.0f * g1;
                    float tp = D6;
                    tp = fmaf(v - 5.0f, tp, D5);
                    tp = fmaf(v - 4.0f, tp, D4);
                    tp = fmaf(v - 3.0f, tp, D3);
                    tp = fmaf(v - 2.0f, tp, D2);
                    tp = fmaf(v - 1.0f, tp, D1);
                    const float g2 = fmaf(v, tp, F0);
                    res[e] = fmaf(1.0f - g2, P, g2);
                }
                *(float2*)(orow + col) = make_float2(res[0], res[1]);
            }
        }
}

// ---------------------------------------------------------------------------
extern "C" void kernel_launch(void* const* d_in, const int* in_sizes, int n_in,
                              void* d_out, int out_size) {
    const int*   stu_list = (const int*)  d_in[0];
    const float* stu_emb  = (const float*)d_in[1];
    const float* item_emb = (const float*)d_in[2];
    const float* disc     = (const float*)d_in[3];
    const float* Q        = (const float*)d_in[4];
    const float* w1       = (const float*)d_in[5];
    const float* b1       = (const float*)d_in[6];
    const float* wp       = (const float*)d_in[7];
    const float* bp       = (const float*)d_in[8];
    const float* gw_stu   = (const float*)d_in[9];
    const float* gw_Q     = (const float*)d_in[10];
    const float* w2       = (const float*)d_in[11];
    const float* b2       = (const float*)d_in[12];
    float* out = (float*)d_out;

    stu_kernel<<<16, 512>>>(stu_list, stu_emb, w1, b1, gw_stu);

    cudaFuncSetAttribute(main_kernel, cudaFuncAttributeMaxDynamicSharedMemorySize,
                         SMEM_BYTES);
    cudaLaunchConfig_t cfg = {};
    cfg.gridDim  = dim3(NBLK);
    cfg.blockDim = dim3(512);
    cfg.dynamicSmemBytes = SMEM_BYTES;
    cfg.stream = 0;
    cudaLaunchAttribute attrs[1];
    attrs[0].id = cudaLaunchAttributeProgrammaticStreamSerialization;
    attrs[0].val.programmaticStreamSerializationAllowed = 1;
    cfg.attrs = attrs;
    cfg.numAttrs = 1;
    cudaLaunchKernelEx(&cfg, main_kernel, item_emb, disc, Q, w1, b1, wp, bp,
                       gw_Q, w2, b2, out);
}

// round 11
// speedup vs baseline: 1.3909x; 1.0151x over previous
#include <cuda_runtime.h>
#include <cuda_fp16.h>
#include <cstdint>

#define BATCH 128
#define ITEMS 8000
#define CONC  128
#define EMB   32
#define TI    32
#define NBLK  (ITEMS / TI)    // 250

#define W1S 36      // w1 row stride (floats)
#define IES 36      // item_emb row stride (floats)
#define QWHS 136    // qw' row stride (halves)

// float-offset smem map
#define OFF_AH   0        // A' fp16 fragment blocks: 16384 halves = 8192 floats
#define OFF_QWH  8192     // qw' fp16: 32*136 halves = 2176 floats
#define OFF_W1   10368    // 128*36
#define OFF_IE   14976    // 32*36
#define OFF_B1   16128    // 128
#define OFF_WP   16256    // 128
#define OFF_GQ   16384    // 128
#define OFF_ZC   16512    // 32
#define OFF_QA   16544    // 32
#define OFF_DISC 16576    // 32
#define OFF_GSU  16608    // 128
#define OFF_POLY 16736    // 8
#define SMEM_FLOATS 16744
#define SMEM_BYTES  (SMEM_FLOATS * 4)   // 66976 B -> 2 CTAs/SM

__device__ __half g_stuC[BATCH * CONC];  // fp16, fragment-block order
__device__ float  g_gsu[BATCH];

__device__ __forceinline__ float sigmoidf(float x) {
    return __fdividef(1.0f, 1.0f + __expf(-x));
}
__device__ __forceinline__ float sigt(float x) {
    float t;
    asm("tanh.approx.f32 %0, %1;" : "=f"(t) : "f"(x * 0.5f));
    return fmaf(0.5f, t, 0.5f);
}
__device__ __forceinline__ void fma2(unsigned long long& acc,
                                     unsigned long long a, unsigned long long b) {
    asm("fma.rn.f32x2 %0, %1, %2, %0;" : "+l"(acc) : "l"(a), "l"(b));
}
__device__ __forceinline__ void mma_f16(float* d, const uint4 a, const uint2 b) {
    asm("mma.sync.aligned.m16n8k16.row.col.f32.f16.f16.f32 "
        "{%0,%1,%2,%3}, {%4,%5,%6,%7}, {%8,%9}, {%0,%1,%2,%3};"
        : "+f"(d[0]), "+f"(d[1]), "+f"(d[2]), "+f"(d[3])
        : "r"(a.x), "r"(a.y), "r"(a.z), "r"(a.w), "r"(b.x), "r"(b.y));
}
__device__ __forceinline__ void cp16(float* dst_smem, const void* src) {
    unsigned d = (unsigned)__cvta_generic_to_shared(dst_smem);
    asm volatile("cp.async.ca.shared.global [%0], [%1], 16;\n" :: "r"(d), "l"(src));
}
// fragment-block half index for stuC[b][c]  (m16n8k16 A fragment order)
__device__ __forceinline__ int fragIdxH(int b, int c) {
    const int blk  = (b >> 4) * 8 + (c >> 4);
    const int rr   = b & 7;
    const int hi8  = (b >> 3) & 1;
    const int c15  = c & 15;
    const int tigc = (c15 >> 1) & 3;
    const int khi  = (c15 >> 3) & 1;
    const int lo   = c15 & 1;
    return blk * 256 + (rr * 4 + tigc) * 8 + (khi * 2 + hi8) * 2 + lo;
}

// ---------------------------------------------------------------------------
// Kernel 1: 16 CTAs x 512 thr; 8 students each. Fragment-order fp16 output.
// ---------------------------------------------------------------------------
__global__ void __launch_bounds__(512) stu_kernel(
    const int*   __restrict__ stu_list,
    const float* __restrict__ stu_emb,
    const float* __restrict__ w1,
    const float* __restrict__ b1,
    const float* __restrict__ gw_stu)
{
    __shared__ float s_w1[CONC * 33];
    __shared__ float s_emb[8 * EMB];
    __shared__ int   s_sidx[8];

    asm volatile("griddepcontrol.launch_dependents;");

    const int t  = threadIdx.x;
    const int b0 = blockIdx.x * 8;

    if (t < 8) {
        const int idx = stu_list[b0 + t] - 1;
        s_sidx[t] = idx;
        g_gsu[b0 + t] = gw_stu[idx];
    }
    for (int j = t; j < CONC * EMB; j += 512)
        s_w1[(j >> 5) * 33 + (j & 31)] = w1[j];
    __syncthreads();
    if (t < 8 * EMB)
        s_emb[t] = stu_emb[(size_t)s_sidx[t >> 5] * EMB + (t & 31)];
    __syncthreads();

    const int c  = t & 127;
    const int sl = t >> 7;
    const float b1c = b1[c];
#pragma unroll
    for (int r = 0; r < 2; r++) {
        const int s = sl + 4 * r;
        float z = b1c;
#pragma unroll
        for (int k = 0; k < EMB; k++)
            z = fmaf(s_emb[s * EMB + k], s_w1[c * 33 + k], z);
        g_stuC[fragIdxH(b0 + s, c)] = __float2half(sigmoidf(z));
    }
}

// ---------------------------------------------------------------------------
// Kernel 2 (PDL dependent): 250 CTAs x 512 thr, 32 items each, 2 CTAs/SM.
// ---------------------------------------------------------------------------
__global__ void __launch_bounds__(512, 2) main_kernel(
    const float* __restrict__ item_emb,
    const float* __restrict__ disc,
    const float* __restrict__ Q,
    const float* __restrict__ w1,
    const float* __restrict__ b1,
    const float* __restrict__ wp,
    const float* __restrict__ bp,
    const float* __restrict__ gw_Q,
    const float* __restrict__ w2,
    const float* __restrict__ b2,
    float* __restrict__ out)
{
    extern __shared__ float sm[];
    __half* s_Ah  = (__half*)(sm + OFF_AH);
    __half* s_qwh = (__half*)(sm + OFF_QWH);
    float* s_w1   = sm + OFF_W1;
    float* s_ie   = sm + OFF_IE;
    float* s_b1   = sm + OFF_B1;
    float* s_wp   = sm + OFF_WP;
    float* s_gq   = sm + OFF_GQ;
    float* s_zc   = sm + OFF_ZC;
    float* s_qa   = sm + OFF_QA;
    float* s_disc = sm + OFF_DISC;
    float* s_gsu  = sm + OFF_GSU;
    float* s_poly = sm + OFF_POLY;

    const int tid  = threadIdx.x;
    const int wid  = tid >> 5;
    const int lane = tid & 31;
    const int i0   = blockIdx.x * TI;

    // ---- group 0: phase-B inputs (independent of stu_kernel) ----
    for (int j = tid; j < CONC * 8; j += 512)
        cp16(s_w1 + (j >> 3) * W1S + (j & 7) * 4, w1 + j * 4);
    for (int j = tid; j < TI * 8; j += 512)
        cp16(s_ie + (j >> 3) * IES + (j & 7) * 4,
             item_emb + (size_t)i0 * EMB + j * 4);
    if (tid < 32)       cp16(s_b1 + tid * 4, b1 + tid * 4);
    else if (tid < 64)  cp16(s_wp + (tid - 32) * 4, wp + (tid - 32) * 4);
    else if (tid < 96)  cp16(s_gq + (tid - 64) * 4, gw_Q + (tid - 64) * 4);
    else if (tid < 104) cp16(s_disc + (tid - 96) * 4, disc + i0 + (tid - 96) * 4);
    asm volatile("cp.async.commit_group;\n" ::: "memory");

    const float bpv = bp[0];

    // ---- g2 degree-6 Newton interpolation setup (warp 0) ----
    if (wid == 0) {
        const float w2v = w2[0];
        const float b2v = b2[0];
        const float h = 1.0f / 6.0f;
        float fk = sigmoidf(fmaf(w2v, h * (float)(lane < 7 ? lane : 0), b2v));
        const float f0 = __shfl_sync(0xffffffffu, fk, 0);
        const float f1 = __shfl_sync(0xffffffffu, fk, 1);
        const float f2 = __shfl_sync(0xffffffffu, fk, 2);
        const float f3 = __shfl_sync(0xffffffffu, fk, 3);
        const float f4 = __shfl_sync(0xffffffffu, fk, 4);
        const float f5 = __shfl_sync(0xffffffffu, fk, 5);
        const float f6 = __shfl_sync(0xffffffffu, fk, 6);
        if (lane == 0) {
            const float d1 = f1 - f0;
            const float d2 = f2 - 2.0f * f1 + f0;
            const float d3 = f3 - 3.0f * f2 + 3.0f * f1 - f0;
            const float d4 = f4 - 4.0f * f3 + 6.0f * f2 - 4.0f * f1 + f0;
            const float d5 = f5 - 5.0f * f4 + 10.0f * f3 - 10.0f * f2
                             + 5.0f * f1 - f0;
            const float d6 = f6 - 6.0f * f5 + 15.0f * f4 - 20.0f * f3
                             + 15.0f * f2 - 6.0f * f1 + f0;
            s_poly[0] = f0;
            s_poly[1] = d1;
            s_poly[2] = d2 * 0.5f;
            s_poly[3] = d3 * (1.0f / 6.0f);
            s_poly[4] = d4 * (1.0f / 24.0f);
            s_poly[5] = d5 * (1.0f / 120.0f);
            s_poly[6] = d6 * (1.0f / 720.0f);
        }
    }

    asm volatile("cp.async.wait_group 0;\n" ::: "memory");
    __syncthreads();

    // ---- phase B: item ii = tid>>4, concepts c = (tid&15) + 16s, s<8 ----
    {
        const int ii = tid >> 4;     // 0..31
        const int cr = tid & 15;
        // qw' in-row slot for this cr (k16-group position)
        const int posr = 4 * ((cr >> 1) & 3) + 2 * ((cr >> 3) & 1) + (cr & 1);

        // batched Q loads (MLP=8)
        float qv[8];
#pragma unroll
        for (int s = 0; s < 8; s++)
            qv[s] = Q[(size_t)(i0 + ii) * CONC + cr + 16 * s];

        ulonglong2 ier[8];
        const ulonglong2* iep = (const ulonglong2*)(s_ie + ii * IES);
#pragma unroll
        for (int k = 0; k < 8; k++) ier[k] = iep[k];

        float prod = 0.0f, qa = 0.0f;
#pragma unroll
        for (int s = 0; s < 8; s++) {
            const int c = cr + 16 * s;
            const ulonglong2* wr = (const ulonglong2*)(s_w1 + c * W1S);
            unsigned long long za = 0ull, zb = 0ull;
#pragma unroll
            for (int k = 0; k < 8; k++) {
                ulonglong2 w = wr[k];
                fma2(za, ier[k].x, w.x);
                fma2(zb, ier[k].y, w.y);
            }
            float la, ha, lb, hb;
            asm("mov.b64 {%0, %1}, %2;" : "=f"(la), "=f"(ha) : "l"(za));
            asm("mov.b64 {%0, %1}, %2;" : "=f"(lb), "=f"(hb) : "l"(zb));
            const float z  = (la + ha) + (lb + hb) + s_b1[c];
            const float ic = sigt(z);
            const float qwv = qv[s] * s_wp[c];
            s_qwh[ii * QWHS + 16 * s + posr] = __float2half(qwv);
            prod = fmaf(qwv, ic, prod);
            qa   = fmaf(qv[s], s_gq[c], qa);
        }
#pragma unroll
        for (int off = 8; off > 0; off >>= 1) {
            prod += __shfl_down_sync(0xffffffffu, prod, off, 16);
            qa   += __shfl_down_sync(0xffffffffu, qa,   off, 16);
        }
        if (cr == 0) {
            s_zc[ii] = fmaf(-s_disc[ii], prod, bpv);
            s_qa[ii] = qa;
        }
    }

    // ---- wait for stu_kernel, pull A' (fp16) + gsu ----
    asm volatile("griddepcontrol.wait;" ::: "memory");
    for (int j = tid; j < 2048; j += 512)      // 32768 B = 2048 x 16B
        cp16((float*)(s_Ah + j * 8), (const char*)g_stuC + j * 16);
    if (tid < 32) cp16(s_gsu + tid * 4, g_gsu + tid * 4);
    asm volatile("cp.async.commit_group;\n" ::: "memory");
    asm volatile("cp.async.wait_group 0;\n" ::: "memory");
    __syncthreads();

    // ---- phase C: mma.m16n8k16.f16, warp tile 16(b) x 16(i) ----
    const int wm  = wid >> 1;      // 0..7 -> rows 16*wm..+16
    const int wn  = wid & 1;       // 0..1 -> cols 16*wn..+16
    const int gid = lane >> 2;
    const int tig = lane & 3;

    float acc[2][4];
#pragma unroll
    for (int ni = 0; ni < 2; ni++)
#pragma unroll
        for (int r = 0; r < 4; r++) acc[ni][r] = 0.0f;

    const __half* pa = s_Ah + wm * 2048 + (gid * 4 + tig) * 8;
    const __half* pb0 = s_qwh + (16 * wn + gid) * QWHS + 4 * tig;
#pragma unroll
    for (int kb = 0; kb < 8; kb++) {
        const uint4 a  = *(const uint4*)(pa + kb * 256);
        const uint2 b0 = *(const uint2*)(pb0 + kb * 16);
        const uint2 b1v = *(const uint2*)(pb0 + 8 * QWHS + kb * 16);
        mma_f16(acc[0], a, b0);
        mma_f16(acc[1], a, b1v);
    }

    // ---- fused epilogue ----
    const float F0 = s_poly[0], D1 = s_poly[1], D2 = s_poly[2],
                D3 = s_poly[3], D4 = s_poly[4], D5 = s_poly[5],
                D6 = s_poly[6];
#pragma unroll
    for (int h = 0; h < 2; h++) {
        const int row = 16 * wm + 8 * h + gid;
        const float gs = s_gsu[row];
        float* orow = out + (size_t)row * ITEMS + i0;
#pragma unroll
        for (int ni = 0; ni < 2; ni++) {
            const int col = 16 * wn + 8 * ni + 2 * tig;
            float res[2];
#pragma unroll
            for (int e = 0; e < 2; e++) {
                const int il = col + e;
                const float t1 = acc[ni][2 * h + e];
                const float z  = fmaf(s_disc[il], t1, s_zc[il]);
                const float P  = sigt(z);
                const float g1 = sigt(gs + s_qa[il]);
                const float v = 6.0f * g1;
                float tp = D6;
                tp = fmaf(v - 5.0f, tp, D5);
                tp = fmaf(v - 4.0f, tp, D4);
                tp = fmaf(v - 3.0f, tp, D3);
                tp = fmaf(v - 2.0f, tp, D2);
                tp = fmaf(v - 1.0f, tp, D1);
                const float g2 = fmaf(v, tp, F0);
                res[e] = fmaf(1.0f - g2, P, g2);
            }
            *(float2*)(orow + col) = make_float2(res[0], res[1]);
        }
    }
}

// ---------------------------------------------------------------------------
extern "C" void kernel_launch(void* const* d_in, const int* in_sizes, int n_in,
                              void* d_out, int out_size) {
    const int*   stu_list = (const int*)  d_in[0];
    const float* stu_emb  = (const float*)d_in[1];
    const float* item_emb = (const float*)d_in[2];
    const float* disc     = (const float*)d_in[3];
    const float* Q        = (const float*)d_in[4];
    const float* w1       = (const float*)d_in[5];
    const float* b1       = (const float*)d_in[6];
    const float* wp       = (const float*)d_in[7];
    const float* bp       = (const float*)d_in[8];
    const float* gw_stu   = (const float*)d_in[9];
    const float* gw_Q     = (const float*)d_in[10];
    const float* w2       = (const float*)d_in[11];
    const float* b2       = (const float*)d_in[12];
    float* out = (float*)d_out;

    stu_kernel<<<16, 512>>>(stu_list, stu_emb, w1, b1, gw_stu);

    cudaFuncSetAttribute(main_kernel, cudaFuncAttributeMaxDynamicSharedMemorySize,
                         SMEM_BYTES);
    cudaLaunchConfig_t cfg = {};
    cfg.gridDim  = dim3(NBLK);
    cfg.blockDim = dim3(512);
    cfg.dynamicSmemBytes = SMEM_BYTES;
    cfg.stream = 0;
    cudaLaunchAttribute attrs[1];
    attrs[0].id = cudaLaunchAttributeProgrammaticStreamSerialization;
    attrs[0].val.programmaticStreamSerializationAllowed = 1;
    cfg.attrs = attrs;
    cfg.numAttrs = 1;
    cudaLaunchKernelEx(&cfg, main_kernel, item_emb, disc, Q, w1, b1, wp, bp,
                       gw_Q, w2, b2, out);
}

// round 12
// speedup vs baseline: 1.5823x; 1.1376x over previous
#include <cuda_runtime.h>
#include <cuda_fp16.h>
#include <cstdint>

#define BATCH 128
#define ITEMS 8000
#define CONC  128
#define EMB   32
#define TI    32
#define NBLK  (ITEMS / TI)    // 250

#define QWHS 136    // qw' row stride (halves)
#define W1HS 40     // w1h row stride (halves) - conflict-free frag loads
#define IEHS 40     // ieh row stride (halves)

// float-offset smem map
#define OFF_AH   0        // A' fp16 fragment blocks: 16384 halves
#define OFF_QWH  8192     // qw' fp16: 32*136 halves = 2176 floats
#define OFF_W1H  10368    // 128*40 halves = 2560 floats
#define OFF_IEH  12928    // 32*40 halves  = 640 floats
#define OFF_PART 13568    // 16*32 prod partials
#define OFF_PARTQ 14080   // 16*32 qa partials
#define OFF_B1   14592    // 128
#define OFF_WP   14720    // 128
#define OFF_GQ   14848    // 128
#define OFF_ZC   14976    // 32
#define OFF_QA   15008    // 32
#define OFF_DISC 15040    // 32
#define OFF_GSU  15072    // 128
#define OFF_POLY 15200    // 8
#define SMEM_FLOATS 15208
#define SMEM_BYTES  (SMEM_FLOATS * 4)   // 60832 B -> 2 CTAs/SM

__device__ __half g_stuC[BATCH * CONC];  // fp16, fragment-block order
__device__ float  g_gsu[BATCH];

__device__ __forceinline__ float sigmoidf(float x) {
    return __fdividef(1.0f, 1.0f + __expf(-x));
}
__device__ __forceinline__ float sigt(float x) {
    float t;
    asm("tanh.approx.f32 %0, %1;" : "=f"(t) : "f"(x * 0.5f));
    return fmaf(0.5f, t, 0.5f);
}
__device__ __forceinline__ void mma_f16(float* d, const uint4 a, const uint2 b) {
    asm("mma.sync.aligned.m16n8k16.row.col.f32.f16.f16.f32 "
        "{%0,%1,%2,%3}, {%4,%5,%6,%7}, {%8,%9}, {%0,%1,%2,%3};"
        : "+f"(d[0]), "+f"(d[1]), "+f"(d[2]), "+f"(d[3])
        : "r"(a.x), "r"(a.y), "r"(a.z), "r"(a.w), "r"(b.x), "r"(b.y));
}
__device__ __forceinline__ void cp16(float* dst_smem, const void* src) {
    unsigned d = (unsigned)__cvta_generic_to_shared(dst_smem);
    asm volatile("cp.async.ca.shared.global [%0], [%1], 16;\n" :: "r"(d), "l"(src));
}
// fragment-block half index for stuC[b][c]  (m16n8k16 A fragment order)
__device__ __forceinline__ int fragIdxH(int b, int c) {
    const int blk  = (b >> 4) * 8 + (c >> 4);
    const int rr   = b & 7;
    const int hi8  = (b >> 3) & 1;
    const int c15  = c & 15;
    const int tigc = (c15 >> 1) & 3;
    const int khi  = (c15 >> 3) & 1;
    const int lo   = c15 & 1;
    return blk * 256 + (rr * 4 + tigc) * 8 + (khi * 2 + hi8) * 2 + lo;
}

// ---------------------------------------------------------------------------
// Kernel 1: 16 CTAs x 512 thr; 8 students each. Fragment-order fp16 output.
// ---------------------------------------------------------------------------
__global__ void __launch_bounds__(512) stu_kernel(
    const int*   __restrict__ stu_list,
    const float* __restrict__ stu_emb,
    const float* __restrict__ w1,
    const float* __restrict__ b1,
    const float* __restrict__ gw_stu)
{
    __shared__ float s_w1[CONC * 33];
    __shared__ float s_emb[8 * EMB];
    __shared__ int   s_sidx[8];

    asm volatile("griddepcontrol.launch_dependents;");

    const int t  = threadIdx.x;
    const int b0 = blockIdx.x * 8;

    if (t < 8) {
        const int idx = stu_list[b0 + t] - 1;
        s_sidx[t] = idx;
        g_gsu[b0 + t] = gw_stu[idx];
    }
    for (int j = t; j < CONC * EMB; j += 512)
        s_w1[(j >> 5) * 33 + (j & 31)] = w1[j];
    __syncthreads();
    if (t < 8 * EMB)
        s_emb[t] = stu_emb[(size_t)s_sidx[t >> 5] * EMB + (t & 31)];
    __syncthreads();

    const int c  = t & 127;
    const int sl = t >> 7;
    const float b1c = b1[c];
#pragma unroll
    for (int r = 0; r < 2; r++) {
        const int s = sl + 4 * r;
        float z = b1c;
#pragma unroll
        for (int k = 0; k < EMB; k++)
            z = fmaf(s_emb[s * EMB + k], s_w1[c * 33 + k], z);
        g_stuC[fragIdxH(b0 + s, c)] = __float2half(sigmoidf(z));
    }
}

// ---------------------------------------------------------------------------
// Kernel 2 (PDL dependent): 250 CTAs x 512 thr, 32 items each, 2 CTAs/SM.
// Phase B itemC GEMM is also on tensor cores now.
// ---------------------------------------------------------------------------
__global__ void __launch_bounds__(512, 2) main_kernel(
    const float* __restrict__ item_emb,
    const float* __restrict__ disc,
    const float* __restrict__ Q,
    const float* __restrict__ w1,
    const float* __restrict__ b1,
    const float* __restrict__ wp,
    const float* __restrict__ bp,
    const float* __restrict__ gw_Q,
    const float* __restrict__ w2,
    const float* __restrict__ b2,
    float* __restrict__ out)
{
    extern __shared__ float sm[];
    __half* s_Ah   = (__half*)(sm + OFF_AH);
    __half* s_qwh  = (__half*)(sm + OFF_QWH);
    __half* s_w1h  = (__half*)(sm + OFF_W1H);
    __half* s_ieh  = (__half*)(sm + OFF_IEH);
    float* s_part  = sm + OFF_PART;
    float* s_partq = sm + OFF_PARTQ;
    float* s_b1    = sm + OFF_B1;
    float* s_wp    = sm + OFF_WP;
    float* s_gq    = sm + OFF_GQ;
    float* s_zc    = sm + OFF_ZC;
    float* s_qa    = sm + OFF_QA;
    float* s_disc  = sm + OFF_DISC;
    float* s_gsu   = sm + OFF_GSU;
    float* s_poly  = sm + OFF_POLY;

    const int tid  = threadIdx.x;
    const int wid  = tid >> 5;
    const int lane = tid & 31;
    const int gid  = lane >> 2;
    const int tig  = lane & 3;
    const int i0   = blockIdx.x * TI;

    // ---- cp.async: fp32 params ----
    if (tid < 32)       cp16(s_b1 + tid * 4, b1 + tid * 4);
    else if (tid < 64)  cp16(s_wp + (tid - 32) * 4, wp + (tid - 32) * 4);
    else if (tid < 96)  cp16(s_gq + (tid - 64) * 4, gw_Q + (tid - 64) * 4);
    else if (tid < 104) cp16(s_disc + (tid - 96) * 4, disc + i0 + (tid - 96) * 4);
    asm volatile("cp.async.commit_group;\n" ::: "memory");

    // ---- fp32 -> fp16 conversions into fragment-friendly strided tiles ----
    for (int j = tid; j < 2048; j += 512) {                // w1: 16KB
        const float2 v = ((const float2*)w1)[j];
        *(__half2*)(s_w1h + (j >> 4) * W1HS + 2 * (j & 15)) =
            __floats2half2_rn(v.x, v.y);
    }
    {
        const int j = tid;                                 // ie: 4KB (512 f2)
        if (j < 512) {
            const float2 v = ((const float2*)(item_emb + (size_t)i0 * EMB))[j];
            *(__half2*)(s_ieh + (j >> 4) * IEHS + 2 * (j & 15)) =
                __floats2half2_rn(v.x, v.y);
        }
    }

    const float bpv = bp[0];

    // ---- g2 degree-6 Newton interpolation setup (warp 0) ----
    if (wid == 0) {
        const float w2v = w2[0];
        const float b2v = b2[0];
        const float h = 1.0f / 6.0f;
        float fk = sigmoidf(fmaf(w2v, h * (float)(lane < 7 ? lane : 0), b2v));
        const float f0 = __shfl_sync(0xffffffffu, fk, 0);
        const float f1 = __shfl_sync(0xffffffffu, fk, 1);
        const float f2 = __shfl_sync(0xffffffffu, fk, 2);
        const float f3 = __shfl_sync(0xffffffffu, fk, 3);
        const float f4 = __shfl_sync(0xffffffffu, fk, 4);
        const float f5 = __shfl_sync(0xffffffffu, fk, 5);
        const float f6 = __shfl_sync(0xffffffffu, fk, 6);
        if (lane == 0) {
            const float d1 = f1 - f0;
            const float d2 = f2 - 2.0f * f1 + f0;
            const float d3 = f3 - 3.0f * f2 + 3.0f * f1 - f0;
            const float d4 = f4 - 4.0f * f3 + 6.0f * f2 - 4.0f * f1 + f0;
            const float d5 = f5 - 5.0f * f4 + 10.0f * f3 - 10.0f * f2
                             + 5.0f * f1 - f0;
            const float d6 = f6 - 6.0f * f5 + 15.0f * f4 - 20.0f * f3
                             + 15.0f * f2 - 6.0f * f1 + f0;
            s_poly[0] = f0;
            s_poly[1] = d1;
            s_poly[2] = d2 * 0.5f;
            s_poly[3] = d3 * (1.0f / 6.0f);
            s_poly[4] = d4 * (1.0f / 24.0f);
            s_poly[5] = d5 * (1.0f / 120.0f);
            s_poly[6] = d6 * (1.0f / 720.0f);
        }
    }

    asm volatile("cp.async.wait_group 0;\n" ::: "memory");
    __syncthreads();

    // ---- phase B: z[32 items, 128 conc] = ie @ w1^T on tensor cores ----
    // warp wid owns conc slice [8*wid, 8*wid+8); covers all 32 items.
    {
        const int c = 8 * wid + 2 * tig;     // this thread's conc pair base

        // early Q loads for the 4 items x conc pair this thread will own
        float2 qv[4];
#pragma unroll
        for (int s = 0; s < 4; s++) {
            const int item = 8 * s + gid;
            qv[s] = *(const float2*)(Q + (size_t)(i0 + item) * CONC + c);
        }

        float acc[2][4];
#pragma unroll
        for (int mi = 0; mi < 2; mi++)
#pragma unroll
            for (int r = 0; r < 4; r++) acc[mi][r] = 0.0f;

#pragma unroll
        for (int kc = 0; kc < 2; kc++) {
            uint2 bb;
            bb.x = *(const uint32_t*)(s_w1h + (8 * wid + gid) * W1HS + 16 * kc + 2 * tig);
            bb.y = *(const uint32_t*)(s_w1h + (8 * wid + gid) * W1HS + 16 * kc + 2 * tig + 8);
#pragma unroll
            for (int mi = 0; mi < 2; mi++) {
                uint4 aa;
                aa.x = *(const uint32_t*)(s_ieh + (16 * mi + gid) * IEHS + 16 * kc + 2 * tig);
                aa.y = *(const uint32_t*)(s_ieh + (16 * mi + gid + 8) * IEHS + 16 * kc + 2 * tig);
                aa.z = *(const uint32_t*)(s_ieh + (16 * mi + gid) * IEHS + 16 * kc + 2 * tig + 8);
                aa.w = *(const uint32_t*)(s_ieh + (16 * mi + gid + 8) * IEHS + 16 * kc + 2 * tig + 8);
                mma_f16(acc[mi], aa, bb);
            }
        }

        // post-process the 8 (item, conc) cells this thread holds
        const float b1c0 = s_b1[c],  b1c1 = s_b1[c + 1];
        const float wp0  = s_wp[c],  wp1  = s_wp[c + 1];
        const float gq0  = s_gq[c],  gq1  = s_gq[c + 1];
        const int   slot = 16 * (wid >> 1) + 4 * tig + 2 * (wid & 1);

        float pr[4], qa[4];
#pragma unroll
        for (int mi = 0; mi < 2; mi++)
#pragma unroll
            for (int h = 0; h < 2; h++) {
                const int s    = 2 * mi + h;
                const int item = 16 * mi + 8 * h + gid;
                const float z0 = acc[mi][2 * h]     + b1c0;
                const float z1 = acc[mi][2 * h + 1] + b1c1;
                const float ic0 = sigt(z0);
                const float ic1 = sigt(z1);
                const float q0 = (h == 0) ? ((mi == 0) ? qv[0].x : qv[2].x)
                                          : ((mi == 0) ? qv[1].x : qv[3].x);
                const float q1 = (h == 0) ? ((mi == 0) ? qv[0].y : qv[2].y)
                                          : ((mi == 0) ? qv[1].y : qv[3].y);
                const float qw0 = q0 * wp0;
                const float qw1 = q1 * wp1;
                *(__half2*)(s_qwh + item * QWHS + slot) = __floats2half2_rn(qw0, qw1);
                pr[s] = fmaf(qw0, ic0, qw1 * ic1);
                qa[s] = fmaf(q0, gq0, q1 * gq1);
            }
        // reduce over tig (the 8-conc slice), then park partials
#pragma unroll
        for (int s = 0; s < 4; s++) {
            pr[s] += __shfl_down_sync(0xffffffffu, pr[s], 2, 4);
            pr[s] += __shfl_down_sync(0xffffffffu, pr[s], 1, 4);
            qa[s] += __shfl_down_sync(0xffffffffu, qa[s], 2, 4);
            qa[s] += __shfl_down_sync(0xffffffffu, qa[s], 1, 4);
        }
        if (tig == 0) {
#pragma unroll
            for (int mi = 0; mi < 2; mi++)
#pragma unroll
                for (int h = 0; h < 2; h++) {
                    const int item = 16 * mi + 8 * h + gid;
                    s_part [wid * 32 + item] = pr[2 * mi + h];
                    s_partq[wid * 32 + item] = qa[2 * mi + h];
                }
        }
    }

    // ---- wait for stu_kernel, pull A' (fp16) + gsu ----
    asm volatile("griddepcontrol.wait;" ::: "memory");
    for (int j = tid; j < 2048; j += 512)      // 32768 B = 2048 x 16B
        cp16((float*)(s_Ah + j * 8), (const char*)g_stuC + j * 16);
    if (tid < 32) cp16(s_gsu + tid * 4, g_gsu + tid * 4);
    asm volatile("cp.async.commit_group;\n" ::: "memory");
    __syncthreads();    // s_part/s_partq/s_qwh visible

    // cross-warp reduce of per-item partials (1 warp)
    if (tid < 32) {
        float t2 = 0.0f, qa = 0.0f;
#pragma unroll
        for (int w = 0; w < 16; w++) {
            t2 += s_part [w * 32 + tid];
            qa += s_partq[w * 32 + tid];
        }
        s_zc[tid] = fmaf(-s_disc[tid], t2, bpv);
        s_qa[tid] = qa;
    }
    asm volatile("cp.async.wait_group 0;\n" ::: "memory");
    __syncthreads();

    // ---- phase C: mma.m16n8k16.f16, warp tile 16(b) x 16(i) ----
    const int wm = wid >> 1;      // rows 16*wm..+16
    const int wn = wid & 1;       // cols 16*wn..+16

    float acc[2][4];
#pragma unroll
    for (int ni = 0; ni < 2; ni++)
#pragma unroll
        for (int r = 0; r < 4; r++) acc[ni][r] = 0.0f;

    const __half* pa  = s_Ah + wm * 2048 + (gid * 4 + tig) * 8;
    const __half* pb0 = s_qwh + (16 * wn + gid) * QWHS + 4 * tig;
#pragma unroll
    for (int kb = 0; kb < 8; kb++) {
        const uint4 a   = *(const uint4*)(pa + kb * 256);
        const uint2 b0  = *(const uint2*)(pb0 + kb * 16);
        const uint2 b1v = *(const uint2*)(pb0 + 8 * QWHS + kb * 16);
        mma_f16(acc[0], a, b0);
        mma_f16(acc[1], a, b1v);
    }

    // ---- fused epilogue ----
    const float F0 = s_poly[0], D1 = s_poly[1], D2 = s_poly[2],
                D3 = s_poly[3], D4 = s_poly[4], D5 = s_poly[5],
                D6 = s_poly[6];
#pragma unroll
    for (int h = 0; h < 2; h++) {
        const int row = 16 * wm + 8 * h + gid;
        const float gs = s_gsu[row];
        float* orow = out + (size_t)row * ITEMS + i0;
#pragma unroll
        for (int ni = 0; ni < 2; ni++) {
            const int col = 16 * wn + 8 * ni + 2 * tig;
            float res[2];
#pragma unroll
            for (int e = 0; e < 2; e++) {
                const int il = col + e;
                const float t1 = acc[ni][2 * h + e];
                const float z  = fmaf(s_disc[il], t1, s_zc[il]);
                const float P  = sigt(z);
                const float g1 = sigt(gs + s_qa[il]);
                const float v = 6.0f * g1;
                float tp = D6;
                tp = fmaf(v - 5.0f, tp, D5);
                tp = fmaf(v - 4.0f, tp, D4);
                tp = fmaf(v - 3.0f, tp, D3);
                tp = fmaf(v - 2.0f, tp, D2);
                tp = fmaf(v - 1.0f, tp, D1);
                const float g2 = fmaf(v, tp, F0);
                res[e] = fmaf(1.0f - g2, P, g2);
            }
            *(float2*)(orow + col) = make_float2(res[0], res[1]);
        }
    }
}

// ---------------------------------------------------------------------------
extern "C" void kernel_launch(void* const* d_in, const int* in_sizes, int n_in,
                              void* d_out, int out_size) {
    const int*   stu_list = (const int*)  d_in[0];
    const float* stu_emb  = (const float*)d_in[1];
    const float* item_emb = (const float*)d_in[2];
    const float* disc     = (const float*)d_in[3];
    const float* Q        = (const float*)d_in[4];
    const float* w1       = (const float*)d_in[5];
    const float* b1       = (const float*)d_in[6];
    const float* wp       = (const float*)d_in[7];
    const float* bp       = (const float*)d_in[8];
    const float* gw_stu   = (const float*)d_in[9];
    const float* gw_Q     = (const float*)d_in[10];
    const float* w2       = (const float*)d_in[11];
    const float* b2       = (const float*)d_in[12];
    float* out = (float*)d_out;

    stu_kernel<<<16, 512>>>(stu_list, stu_emb, w1, b1, gw_stu);

    cudaFuncSetAttribute(main_kernel, cudaFuncAttributeMaxDynamicSharedMemorySize,
                         SMEM_BYTES);
    cudaLaunchConfig_t cfg = {};
    cfg.gridDim  = dim3(NBLK);
    cfg.blockDim = dim3(512);
    cfg.dynamicSmemBytes = SMEM_BYTES;
    cfg.stream = 0;
    cudaLaunchAttribute attrs[1];
    attrs[0].id = cudaLaunchAttributeProgrammaticStreamSerialization;
    attrs[0].val.programmaticStreamSerializationAllowed = 1;
    cfg.attrs = attrs;
    cfg.numAttrs = 1;
    cudaLaunchKernelEx(&cfg, main_kernel, item_emb, disc, Q, w1, b1, wp, bp,
                       gw_Q, w2, b2, out);
}